// round 14
// baseline (speedup 1.0000x reference)
#include <cuda_runtime.h>
#include <cuda_bf16.h>
#include <stdint.h>

#define NN 100000
#define EE 1600000
#define HH 128
#define GG 512
#define CC 10
#define TOT (EE + NN)
#define BNEPS 1e-5f

// padded bf16x2 layout: u32[row][68] (64 k-pairs + 4 pad); row = 272 bytes
#define WSTRIDE 68
#define WELEMS (128 * WSTRIDE)    // 8704 u32 (W tile: 128 n-rows)
#define AELEMS (256 * WSTRIDE)    // 17408 u32 (A tile: 256 rows)

// ---------------- scratch (static device globals; no allocation) ----------------
__device__ int   g_is64;
__device__ int   g_batch32[NN];
__device__ int   g_deg[NN];
__device__ float g_dis[NN];
__device__ int   g_rowstart[NN + 1];
__device__ int   g_fill[NN];
__device__ int   g_blocksum[128];
__device__ int   g_blockoff[128];
__device__ int2  g_csr[TOT];                // (src, norm-bits)
__device__ float g_bufA[(size_t)NN * HH];   // GEMM output (h @ W)
__device__ float g_bufB[(size_t)NN * HH];   // aggregation output (pre-BN)
__device__ float g_psum[256 * HH];
__device__ float g_psq[256 * HH];
__device__ float g_scale[3][HH];
__device__ float g_shift[3][HH];
__device__ float g_pooled[GG * HH];
__device__ int   g_counts[GG];
__device__ float g_scaleP[HH];
__device__ float g_shiftP[HH];
__device__ __align__(16) uint32_t g_Whi32[WELEMS];
__device__ __align__(16) uint32_t g_Wlo32[WELEMS];

// ---------------- split-bf16 helpers ----------------
__device__ __forceinline__ uint32_t pack2(float a, float b, uint32_t& lo) {
    __nv_bfloat16 ha = __float2bfloat16(a), hb = __float2bfloat16(b);
    __nv_bfloat16 la = __float2bfloat16(a - __bfloat162float(ha));
    __nv_bfloat16 lb = __float2bfloat16(b - __bfloat162float(hb));
    lo = (uint32_t)__bfloat16_as_ushort(la) | ((uint32_t)__bfloat16_as_ushort(lb) << 16);
    return (uint32_t)__bfloat16_as_ushort(ha) | ((uint32_t)__bfloat16_as_ushort(hb) << 16);
}

__device__ __forceinline__ void prepW_one(const float* __restrict__ W, int idx) {
    int n = idx >> 6, kp = idx & 63;
    float v0 = W[(size_t)(kp * 2) * 128 + n];
    float v1 = W[(size_t)(kp * 2 + 1) * 128 + n];
    uint32_t lo, hi = pack2(v0, v1, lo);
    g_Whi32[n * WSTRIDE + kp] = hi;
    g_Wlo32[n * WSTRIDE + kp] = lo;
}

// ---------------- fused prologue: detect + prepW(W1) + zero psum + node init ----
__global__ void k_prep0(const void* ei, const void* bt, const float* __restrict__ W) {
    __shared__ int s_is64;
    int tid = threadIdx.x, bid = blockIdx.x;
    if (tid == 0) {
        const long long* p = (const long long*)ei;
        int ok = 1;
        for (int i = 0; i < 64; i++) {
            long long v = p[i];
            if (v < 0 || v >= NN) { ok = 0; break; }
        }
        s_is64 = ok;
        if (bid == 0) g_is64 = ok;
    }
    __syncthreads();
    int idx = bid * 256 + tid;
    if (idx < 128 * 64) prepW_one(W, idx);
    if (idx < 256 * HH) { g_psum[idx] = 0.f; g_psq[idx] = 0.f; }
    if (bid >= 128) {
        int i = (bid - 128) * 256 + tid;
        if (i < NN) {
            g_deg[i] = 1;   // self-loop
            if (s_is64) g_batch32[i] = (int)((const long long*)bt)[i];
            else        g_batch32[i] = ((const int*)bt)[i];
        }
    }
}

__global__ void k_count(const void* ei) {   // degree count straight from edge_index
    int e = blockIdx.x * blockDim.x + threadIdx.x;
    if (e >= EE) return;
    int d;
    if (g_is64) d = (int)((const long long*)ei)[EE + e];
    else        d = ((const int*)ei)[EE + e];
    atomicAdd(&g_deg[d], 1);
}

__global__ void k_scan1() {   // inclusive scan of deg per 1024-chunk; also dis
    __shared__ int s[1024];
    int i = blockIdx.x * 1024 + threadIdx.x;
    int v = (i < NN) ? g_deg[i] : 0;
    if (i < NN) g_dis[i] = rsqrtf((float)v);
    s[threadIdx.x] = v;
    __syncthreads();
    for (int off = 1; off < 1024; off <<= 1) {
        int t = (threadIdx.x >= off) ? s[threadIdx.x - off] : 0;
        __syncthreads();
        s[threadIdx.x] += t;
        __syncthreads();
    }
    if (i < NN) g_rowstart[i] = s[threadIdx.x];
    if (threadIdx.x == 1023) g_blocksum[blockIdx.x] = s[1023];
}

__global__ void k_scan2() {
    __shared__ int s[128];
    int t = threadIdx.x;
    int v = (t < 98) ? g_blocksum[t] : 0;
    s[t] = v;
    __syncthreads();
    for (int off = 1; off < 128; off <<= 1) {
        int tv = (t >= off) ? s[t - off] : 0;
        __syncthreads();
        s[t] += tv;
        __syncthreads();
    }
    g_blockoff[t] = s[t] - v;
}

__global__ void k_scan3() {   // finalize rowstart + insert self-loop + fill=1
    int i = blockIdx.x * 1024 + threadIdx.x;
    if (i < NN) {
        int rs = g_rowstart[i] - g_deg[i] + g_blockoff[blockIdx.x];
        g_rowstart[i] = rs;
        float d = g_dis[i];
        g_csr[rs] = make_int2(i, __float_as_int(d * d));
        g_fill[i] = 1;
        if (i == NN - 1) g_rowstart[NN] = TOT;
    }
}

__global__ void k_build(const void* ei) {
    int e = blockIdx.x * blockDim.x + threadIdx.x;
    if (e >= EE) return;
    int s, d;
    if (g_is64) {
        const long long* p = (const long long*)ei;
        s = (int)p[e];
        d = (int)p[EE + e];
    } else {
        const int* p = (const int*)ei;
        s = p[e];
        d = p[EE + e];
    }
    int p = atomicAdd(&g_fill[d], 1);
    g_csr[g_rowstart[d] + p] = make_int2(s, __float_as_int(g_dis[s] * g_dis[d]));
}

// ---------------- GEMM: M=256 tile, 512 threads, smem-staged split-bf16 HMMA ----
#define MMA_BF16(d, a0, a1, a2, a3, b0, b1)                              \
    asm volatile(                                                        \
        "mma.sync.aligned.m16n8k16.row.col.f32.bf16.bf16.f32 "           \
        "{%0,%1,%2,%3},{%4,%5,%6,%7},{%8,%9},{%0,%1,%2,%3};"             \
        : "+f"(d[0]), "+f"(d[1]), "+f"(d[2]), "+f"(d[3])                 \
        : "r"(a0), "r"(a1), "r"(a2), "r"(a3), "r"(b0), "r"(b1))

#define SMEM_DYN ((2 * AELEMS + 2 * WELEMS) * 4)   // 208896 B

// C[N,128] = T(A)[N,128] @ W[128,128]; T = identity or fused BN(scale,shift)+ReLU.
// CTA: 256 rows, 512 threads (16 warps); warp wid -> rows wid*16..+15, all 128 cols.
template <bool TR>
__device__ __forceinline__ void gemm_mma(const float* __restrict__ A,
                                         float* __restrict__ Cm,
                                         const float* __restrict__ scl,
                                         const float* __restrict__ shf) {
    extern __shared__ uint32_t sm[];
    uint32_t* Ahi = sm;
    uint32_t* Alo = sm + AELEMS;
    uint32_t* Bhi = sm + 2 * AELEMS;
    uint32_t* Blo = sm + 2 * AELEMS + WELEMS;
    __shared__ float s_sc[128], s_sh[128];

    const int tid = threadIdx.x;
    const int row0 = blockIdx.x * 256;

    if (TR && tid < 128) { s_sc[tid] = scl[tid]; s_sh[tid] = shf[tid]; }

    // copy pre-split W into smem (uint4; 2176 uint4 per buffer)
    {
        const uint4* src_h = (const uint4*)g_Whi32;
        const uint4* src_l = (const uint4*)g_Wlo32;
        uint4* dst_h = (uint4*)Bhi;
        uint4* dst_l = (uint4*)Blo;
#pragma unroll
        for (int i = 0; i < 5; i++) {
            int q = tid + i * 512;
            if (q < WELEMS / 4) { dst_h[q] = src_h[q]; dst_l[q] = src_l[q]; }
        }
    }
    if (TR) __syncthreads();   // s_sc/s_sh visible for A staging

    // stage A: thread -> row r = tid/2 (0..255), k-half kh (64 cols)
    {
        int r = tid >> 1;
        int kh = (tid & 1) << 6;
        int gr = row0 + r;
        const float* Arow = A + (size_t)gr * 128;
        uint32_t* ah = Ahi + r * WSTRIDE + (kh >> 1);
        uint32_t* al = Alo + r * WSTRIDE + (kh >> 1);
#pragma unroll
        for (int g = 0; g < 16; g++) {
            int k = kh + g * 4;
            float4 v = make_float4(0.f, 0.f, 0.f, 0.f);
            if (gr < NN) {
                v = *(const float4*)(Arow + k);
                if (TR) {
                    v.x = fmaxf(fmaf(v.x, s_sc[k + 0], s_sh[k + 0]), 0.f);
                    v.y = fmaxf(fmaf(v.y, s_sc[k + 1], s_sh[k + 1]), 0.f);
                    v.z = fmaxf(fmaf(v.z, s_sc[k + 2], s_sh[k + 2]), 0.f);
                    v.w = fmaxf(fmaf(v.w, s_sc[k + 3], s_sh[k + 3]), 0.f);
                }
            }
            uint32_t l0, l1;
            uint32_t h0 = pack2(v.x, v.y, l0);
            uint32_t h1 = pack2(v.z, v.w, l1);
            ah[g * 2] = h0; ah[g * 2 + 1] = h1;
            al[g * 2] = l0; al[g * 2 + 1] = l1;
        }
    }
    __syncthreads();

    // MMA: warp wid -> rows wid*16..+15; 16 n-tiles of 8; 8 k-chunks of 16
    const int wid = tid >> 5, lane = tid & 31;
    const int qr = lane >> 2, ql = lane & 3;
    const int mrow = wid * 16;
    float acc[16][4];
#pragma unroll
    for (int i = 0; i < 16; i++)
#pragma unroll
        for (int j = 0; j < 4; j++) acc[i][j] = 0.f;

    const uint32_t* Ah0 = Ahi + (mrow + qr) * WSTRIDE;
    const uint32_t* Ah1 = Ahi + (mrow + qr + 8) * WSTRIDE;
    const uint32_t* Al0 = Alo + (mrow + qr) * WSTRIDE;
    const uint32_t* Al1 = Alo + (mrow + qr + 8) * WSTRIDE;

#pragma unroll
    for (int kc = 0; kc < 8; kc++) {
        int kb = kc * 8;
        uint32_t ah0 = Ah0[kb + ql],     ah1 = Ah1[kb + ql];
        uint32_t ah2 = Ah0[kb + 4 + ql], ah3 = Ah1[kb + 4 + ql];
        uint32_t al0 = Al0[kb + ql],     al1 = Al1[kb + ql];
        uint32_t al2 = Al0[kb + 4 + ql], al3 = Al1[kb + 4 + ql];
#pragma unroll
        for (int nt = 0; nt < 16; nt++) {
            const uint32_t* Bh = Bhi + (nt * 8 + qr) * WSTRIDE;
            const uint32_t* Bl = Blo + (nt * 8 + qr) * WSTRIDE;
            uint32_t bh0 = Bh[kb + ql], bh1 = Bh[kb + 4 + ql];
            uint32_t bl0 = Bl[kb + ql], bl1 = Bl[kb + 4 + ql];
            MMA_BF16(acc[nt], ah0, ah1, ah2, ah3, bh0, bh1);
            MMA_BF16(acc[nt], ah0, ah1, ah2, ah3, bl0, bl1);
            MMA_BF16(acc[nt], al0, al1, al2, al3, bh0, bh1);
        }
    }

    // epilogue
    int r0 = row0 + mrow + qr;
    int r1 = r0 + 8;
#pragma unroll
    for (int nt = 0; nt < 16; nt++) {
        int c = nt * 8 + ql * 2;
        if (r0 < NN) *(float2*)(Cm + (size_t)r0 * 128 + c) = make_float2(acc[nt][0], acc[nt][1]);
        if (r1 < NN) *(float2*)(Cm + (size_t)r1 * 128 + c) = make_float2(acc[nt][2], acc[nt][3]);
    }
}

__global__ __launch_bounds__(512) void k_gemm_x(const float* __restrict__ A) {
    gemm_mma<false>(A, g_bufA, nullptr, nullptr);
}

template <int L>
__global__ __launch_bounds__(512) void k_gemm_h() {
    gemm_mma<true>(g_bufB, g_bufA, g_scale[L], g_shift[L]);
}

// ---------------- aggregation with fused BN partial stats ----------------
__global__ __launch_bounds__(256) void k_agg() {
    __shared__ float s_red[8][128];
    int gt = blockIdx.x * blockDim.x + threadIdx.x;
    int w = gt >> 5, lane = threadIdx.x & 31, wid = threadIdx.x >> 5;
    int s0 = g_rowstart[w], s1 = g_rowstart[w + 1];
    int fo = lane * 4;
    float4 acc = make_float4(0.f, 0.f, 0.f, 0.f);
    for (int j = s0; j < s1; j++) {
        int2 e = g_csr[j];
        float nm = __int_as_float(e.y);
        float4 v = *(const float4*)(g_bufA + (size_t)e.x * 128 + fo);
        acc.x = fmaf(nm, v.x, acc.x);
        acc.y = fmaf(nm, v.y, acc.y);
        acc.z = fmaf(nm, v.z, acc.z);
        acc.w = fmaf(nm, v.w, acc.w);
    }
    *(float4*)(g_bufB + (size_t)w * 128 + fo) = acc;
    *(float4*)&s_red[wid][fo] = acc;
    __syncthreads();
    int t = threadIdx.x;
    if (t < 128) {
        float s = 0.f, q = 0.f;
#pragma unroll
        for (int r = 0; r < 8; r++) {
            float v = s_red[r][t];
            s += v;
            q = fmaf(v, v, q);
        }
        int slot = (blockIdx.x & 255) * 128 + t;
        atomicAdd(&g_psum[slot], s);
        atomicAdd(&g_psq[slot], q);
    }
}

// ---------------- layer end: BN finalize (+psum re-zero) + prep next W / zero pool ----
template <int L, bool PREPW, bool ZPOOL>
__global__ void k_layer_end(const float* __restrict__ gamma,
                            const float* __restrict__ beta,
                            const float* __restrict__ Wn) {
    int tid = threadIdx.x, bid = blockIdx.x;
    if (bid == 0) {
        if (tid < 128) {
            int f = tid;
            float s = 0.f, q = 0.f;
            for (int b = 0; b < 256; b++) {
                int o = b * 128 + f;
                s += g_psum[o];
                q += g_psq[o];
                g_psum[o] = 0.f;
                g_psq[o] = 0.f;
            }
            float m = s / (float)NN;
            float var = fmaxf(q / (float)NN - m * m, 0.f);
            float sc = gamma[f] * rsqrtf(var + BNEPS);
            g_scale[L][f] = sc;
            g_shift[L][f] = beta[f] - m * sc;   // GCN bias cancels inside BN
        }
    } else {
        int idx = (bid - 1) * 256 + tid;
        if (PREPW) {
            if (idx < 128 * 64) prepW_one(Wn, idx);
        }
        if (ZPOOL) {
            if (idx < GG * HH) g_pooled[idx] = 0.f;
            if (idx < GG) g_counts[idx] = 0;
        }
    }
}

// ---------------- pooling (BN+ReLU fused, segment-accumulated: batch is sorted) ----
__global__ __launch_bounds__(256) void k_pool() {
    int gw = (blockIdx.x * blockDim.x + threadIdx.x) >> 5;
    int lane = threadIdx.x & 31;
    int n0 = gw * 16;
    if (n0 >= NN) return;
    int n1 = n0 + 16;
    if (n1 > NN) n1 = NN;
    int fo = lane * 4;
    float4 sc = *(const float4*)&g_scale[2][fo];
    float4 sh = *(const float4*)&g_shift[2][fo];
    int cur = g_batch32[n0];
    float4 acc = make_float4(0.f, 0.f, 0.f, 0.f);
    int cnt = 0;
    for (int n = n0; n < n1; n++) {
        int gb = g_batch32[n];
        if (gb != cur) {
            float* base = g_pooled + (size_t)cur * 128 + fo;
            atomicAdd(base + 0, acc.x);
            atomicAdd(base + 1, acc.y);
            atomicAdd(base + 2, acc.z);
            atomicAdd(base + 3, acc.w);
            if (lane == 0) atomicAdd(&g_counts[cur], cnt);
            acc = make_float4(0.f, 0.f, 0.f, 0.f);
            cnt = 0;
            cur = gb;
        }
        float4 v = *(const float4*)(g_bufB + (size_t)n * 128 + fo);
        acc.x += fmaxf(fmaf(v.x, sc.x, sh.x), 0.f);
        acc.y += fmaxf(fmaf(v.y, sc.y, sh.y), 0.f);
        acc.z += fmaxf(fmaf(v.z, sc.z, sh.z), 0.f);
        acc.w += fmaxf(fmaf(v.w, sc.w, sh.w), 0.f);
        cnt++;
    }
    float* base = g_pooled + (size_t)cur * 128 + fo;
    atomicAdd(base + 0, acc.x);
    atomicAdd(base + 1, acc.y);
    atomicAdd(base + 2, acc.z);
    atomicAdd(base + 3, acc.w);
    if (lane == 0) atomicAdd(&g_counts[cur], cnt);
}

// ---------------- head ----------------
__global__ void k_headstats(const float* __restrict__ gp,
                            const float* __restrict__ bep) {
    int f = threadIdx.x;
    float s = 0.f, q = 0.f;
    for (int r = 0; r < GG; r++) {
        int c = g_counts[r];
        float invc = 1.f / (float)(c > 0 ? c : 1);
        float v = g_pooled[(size_t)r * 128 + f] * invc;
        s += v;
        q = fmaf(v, v, q);
    }
    float m = s / (float)GG;
    float var = fmaxf(q / (float)GG - m * m, 0.f);
    float sc = gp[f] * rsqrtf(var + BNEPS);
    g_scaleP[f] = sc;
    g_shiftP[f] = bep[f] - m * sc;
}

__global__ void k_head(const float* __restrict__ lw1, const float* __restrict__ lb1,
                       const float* __restrict__ lw2, const float* __restrict__ lb2,
                       float* __restrict__ out) {
    __shared__ float zn[128], y1[128], lg[CC], lse;
    int r = blockIdx.x, t = threadIdx.x;
    int c = g_counts[r];
    float invc = 1.f / (float)(c > 0 ? c : 1);
    zn[t] = fmaf(g_pooled[(size_t)r * 128 + t] * invc, g_scaleP[t], g_shiftP[t]);
    __syncthreads();
    float a = lb1[t];
#pragma unroll 16
    for (int k = 0; k < 128; k++) a = fmaf(zn[k], lw1[(size_t)k * 128 + t], a);
    y1[t] = fmaxf(a, 0.f);
    __syncthreads();
    if (t < CC) {
        float a2 = lb2[t];
#pragma unroll 16
        for (int k = 0; k < 128; k++) a2 = fmaf(y1[k], lw2[(size_t)k * CC + t], a2);
        lg[t] = a2;
    }
    __syncthreads();
    if (t == 0) {
        float m = lg[0];
        for (int i = 1; i < CC; i++) m = fmaxf(m, lg[i]);
        float s = 0.f;
        for (int i = 0; i < CC; i++) s += expf(lg[i] - m);
        lse = m + logf(s);
    }
    __syncthreads();
    if (t < CC) out[(size_t)r * CC + t] = lg[t] - lse;
}

// ---------------- launch ----------------
extern "C" void kernel_launch(void* const* d_in, const int* in_sizes, int n_in,
                              void* d_out, int out_size) {
    const float* x   = (const float*)d_in[0];
    const void*  ei  = d_in[1];
    const void*  bt  = d_in[2];
    const float* W1  = (const float*)d_in[3];
    const float* g1  = (const float*)d_in[5];
    const float* be1 = (const float*)d_in[6];
    const float* W2  = (const float*)d_in[7];
    const float* g2  = (const float*)d_in[9];
    const float* be2 = (const float*)d_in[10];
    const float* W3  = (const float*)d_in[11];
    const float* g3  = (const float*)d_in[13];
    const float* be3 = (const float*)d_in[14];
    const float* gp  = (const float*)d_in[15];
    const float* bep = (const float*)d_in[16];
    const float* lw1 = (const float*)d_in[17];
    const float* lb1 = (const float*)d_in[18];
    const float* lw2 = (const float*)d_in[19];
    const float* lb2 = (const float*)d_in[20];
    float* out = (float*)d_out;

    cudaFuncSetAttribute((const void*)k_gemm_x,
                         cudaFuncAttributeMaxDynamicSharedMemorySize, SMEM_DYN);
    cudaFuncSetAttribute((const void*)k_gemm_h<0>,
                         cudaFuncAttributeMaxDynamicSharedMemorySize, SMEM_DYN);
    cudaFuncSetAttribute((const void*)k_gemm_h<1>,
                         cudaFuncAttributeMaxDynamicSharedMemorySize, SMEM_DYN);

    const int EB  = (EE + 255) / 256;          // 6250
    const int WB  = (NN * 32 + 255) / 256;     // 12500
    const int GMB = (NN + 255) / 256;          // 391 (M=256 tiles)
    const int PB  = ((NN + 15) / 16 + 7) / 8;  // pool: 16 nodes/warp

    k_prep0<<<519, 256>>>(ei, bt, W1);        // detect + prepW(W1) + zero psum + node init
    k_count<<<EB, 256>>>(ei);                 // degree count from edge_index
    k_scan1<<<98, 1024>>>();                  // + dis
    k_gemm_x<<<GMB, 512, SMEM_DYN>>>(x);      // <- profiled launch (slot 4)
    k_scan2<<<1, 128>>>();
    k_scan3<<<98, 1024>>>();                  // + self-loop insert
    k_build<<<EB, 256>>>(ei);

    // layer 1
    k_agg<<<WB, 256>>>();
    k_layer_end<0, true, false><<<33, 256>>>(g1, be1, W2);
    // layer 2 (BN+ReLU of layer 1 fused into GEMM A staging)
    k_gemm_h<0><<<GMB, 512, SMEM_DYN>>>();
    k_agg<<<WB, 256>>>();
    k_layer_end<1, true, false><<<33, 256>>>(g2, be2, W3);
    // layer 3
    k_gemm_h<1><<<GMB, 512, SMEM_DYN>>>();
    k_agg<<<WB, 256>>>();
    k_layer_end<2, false, true><<<257, 256>>>(g3, be3, nullptr);

    // pool + head
    k_pool<<<PB, 256>>>();
    k_headstats<<<1, 128>>>(gp, bep);
    k_head<<<GG, 128>>>(lw1, lb1, lw2, lb2, out);
}

// round 16
// speedup vs baseline: 1.1134x; 1.1134x over previous
#include <cuda_runtime.h>
#include <cuda_bf16.h>
#include <cuda_fp16.h>
#include <stdint.h>

#define NN 100000
#define EE 1600000
#define HH 128
#define GG 512
#define CC 10
#define TOT (EE + NN)
#define BNEPS 1e-5f

// W^T padded bf16x2 layout: u32[n][68] (64 k-pairs + 4 pad); row = 272 bytes
#define WSTRIDE 68
#define WELEMS (128 * WSTRIDE)   // 8704 u32

// ---------------- scratch (static device globals; no allocation) ----------------
__device__ int   g_is64;
__device__ int   g_batch32[NN];
__device__ int   g_deg[NN];
__device__ float g_dis[NN];
__device__ int   g_rowstart[NN + 1];
__device__ int   g_fill[NN];
__device__ int   g_blocksum[128];
__device__ int   g_blockoff[128];
__device__ int2  g_csr[TOT];                    // (src, norm-bits)
__device__ uint32_t g_bufA16[(size_t)NN * 64];  // GEMM output, fp16x2 (feature pairs)
__device__ float g_bufB[(size_t)NN * HH];       // aggregation output (pre-BN, fp32)
__device__ float g_psum[256 * HH];
__device__ float g_psq[256 * HH];
__device__ float g_scale[3][HH];
__device__ float g_shift[3][HH];
__device__ float g_pooled[GG * HH];
__device__ int   g_counts[GG];
__device__ float g_scaleP[HH];
__device__ float g_shiftP[HH];
__device__ __align__(16) uint32_t g_Whi32[WELEMS];
__device__ __align__(16) uint32_t g_Wlo32[WELEMS];

// ---------------- split-bf16 helpers ----------------
__device__ __forceinline__ uint32_t pack2(float a, float b, uint32_t& lo) {
    __nv_bfloat16 ha = __float2bfloat16(a), hb = __float2bfloat16(b);
    __nv_bfloat16 la = __float2bfloat16(a - __bfloat162float(ha));
    __nv_bfloat16 lb = __float2bfloat16(b - __bfloat162float(hb));
    lo = (uint32_t)__bfloat16_as_ushort(la) | ((uint32_t)__bfloat16_as_ushort(lb) << 16);
    return (uint32_t)__bfloat16_as_ushort(ha) | ((uint32_t)__bfloat16_as_ushort(hb) << 16);
}

__device__ __forceinline__ uint32_t packhf(float a, float b) {
    __half2 h2 = __floats2half2_rn(a, b);
    return *reinterpret_cast<uint32_t*>(&h2);
}

__device__ __forceinline__ void prepW_one(const float* __restrict__ W, int idx) {
    int n = idx >> 6, kp = idx & 63;
    float v0 = W[(size_t)(kp * 2) * 128 + n];
    float v1 = W[(size_t)(kp * 2 + 1) * 128 + n];
    uint32_t lo, hi = pack2(v0, v1, lo);
    g_Whi32[n * WSTRIDE + kp] = hi;
    g_Wlo32[n * WSTRIDE + kp] = lo;
}

// ---------------- fused prologue: detect + prepW(W1) + zero psum + node init ----
__global__ void k_prep0(const void* ei, const void* bt, const float* __restrict__ W) {
    __shared__ int s_is64;
    int tid = threadIdx.x, bid = blockIdx.x;
    if (tid == 0) {
        const long long* p = (const long long*)ei;
        int ok = 1;
        for (int i = 0; i < 64; i++) {
            long long v = p[i];
            if (v < 0 || v >= NN) { ok = 0; break; }
        }
        s_is64 = ok;
        if (bid == 0) g_is64 = ok;
    }
    __syncthreads();
    int idx = bid * 256 + tid;
    if (idx < 128 * 64) prepW_one(W, idx);
    if (idx < 256 * HH) { g_psum[idx] = 0.f; g_psq[idx] = 0.f; }
    if (bid >= 128) {
        int i = (bid - 128) * 256 + tid;
        if (i < NN) {
            g_deg[i] = 1;   // self-loop
            if (s_is64) g_batch32[i] = (int)((const long long*)bt)[i];
            else        g_batch32[i] = ((const int*)bt)[i];
        }
    }
}

__global__ void k_count(const void* ei) {   // degree count straight from edge_index
    int e = blockIdx.x * blockDim.x + threadIdx.x;
    if (e >= EE) return;
    int d;
    if (g_is64) d = (int)((const long long*)ei)[EE + e];
    else        d = ((const int*)ei)[EE + e];
    atomicAdd(&g_deg[d], 1);
}

__global__ void k_scan1() {   // inclusive scan of deg per 1024-chunk; also dis
    __shared__ int s[1024];
    int i = blockIdx.x * 1024 + threadIdx.x;
    int v = (i < NN) ? g_deg[i] : 0;
    if (i < NN) g_dis[i] = rsqrtf((float)v);
    s[threadIdx.x] = v;
    __syncthreads();
    for (int off = 1; off < 1024; off <<= 1) {
        int t = (threadIdx.x >= off) ? s[threadIdx.x - off] : 0;
        __syncthreads();
        s[threadIdx.x] += t;
        __syncthreads();
    }
    if (i < NN) g_rowstart[i] = s[threadIdx.x];
    if (threadIdx.x == 1023) g_blocksum[blockIdx.x] = s[1023];
}

__global__ void k_scan2() {
    __shared__ int s[128];
    int t = threadIdx.x;
    int v = (t < 98) ? g_blocksum[t] : 0;
    s[t] = v;
    __syncthreads();
    for (int off = 1; off < 128; off <<= 1) {
        int tv = (t >= off) ? s[t - off] : 0;
        __syncthreads();
        s[t] += tv;
        __syncthreads();
    }
    g_blockoff[t] = s[t] - v;
}

__global__ void k_scan3() {   // finalize rowstart + insert self-loop + fill=1
    int i = blockIdx.x * 1024 + threadIdx.x;
    if (i < NN) {
        int rs = g_rowstart[i] - g_deg[i] + g_blockoff[blockIdx.x];
        g_rowstart[i] = rs;
        float d = g_dis[i];
        g_csr[rs] = make_int2(i, __float_as_int(d * d));
        g_fill[i] = 1;
        if (i == NN - 1) g_rowstart[NN] = TOT;
    }
}

__global__ void k_build(const void* ei) {
    int e = blockIdx.x * blockDim.x + threadIdx.x;
    if (e >= EE) return;
    int s, d;
    if (g_is64) {
        const long long* p = (const long long*)ei;
        s = (int)p[e];
        d = (int)p[EE + e];
    } else {
        const int* p = (const int*)ei;
        s = p[e];
        d = p[EE + e];
    }
    int p = atomicAdd(&g_fill[d], 1);
    g_csr[g_rowstart[d] + p] = make_int2(s, __float_as_int(g_dis[s] * g_dis[d]));
}

// ---------------- GEMM (R4 geometry: M=128/256t, smem-staged, split-bf16 HMMA) ----
#define MMA_BF16(d, a0, a1, a2, a3, b0, b1)                              \
    asm volatile(                                                        \
        "mma.sync.aligned.m16n8k16.row.col.f32.bf16.bf16.f32 "           \
        "{%0,%1,%2,%3},{%4,%5,%6,%7},{%8,%9},{%0,%1,%2,%3};"             \
        : "+f"(d[0]), "+f"(d[1]), "+f"(d[2]), "+f"(d[3])                 \
        : "r"(a0), "r"(a1), "r"(a2), "r"(a3), "r"(b0), "r"(b1))

#define SMEM_DYN (4 * WELEMS * 4)   // Ahi, Alo, Bhi, Blo = 139264 B

// bufA16[N,64 pairs] = T(A)[N,128] @ W[128,128]; T = identity or BN(scale,shift)+ReLU.
template <bool TR>
__device__ __forceinline__ void gemm_mma(const float* __restrict__ A,
                                         const float* __restrict__ scl,
                                         const float* __restrict__ shf) {
    extern __shared__ uint32_t sm[];
    uint32_t* Ahi = sm;
    uint32_t* Alo = sm + WELEMS;
    uint32_t* Bhi = sm + 2 * WELEMS;
    uint32_t* Blo = sm + 3 * WELEMS;
    __shared__ float s_sc[128], s_sh[128];

    const int tid = threadIdx.x;
    const int row0 = blockIdx.x * 128;

    if (TR && tid < 128) { s_sc[tid] = scl[tid]; s_sh[tid] = shf[tid]; }

    // copy pre-split W into smem (uint4; 2176 uint4 per buffer)
    {
        const uint4* src_h = (const uint4*)g_Whi32;
        const uint4* src_l = (const uint4*)g_Wlo32;
        uint4* dst_h = (uint4*)Bhi;
        uint4* dst_l = (uint4*)Blo;
#pragma unroll
        for (int i = 0; i < 9; i++) {
            int q = tid + i * 256;
            if (q < WELEMS / 4) { dst_h[q] = src_h[q]; dst_l[q] = src_l[q]; }
        }
    }
    if (TR) __syncthreads();   // s_sc/s_sh visible for A staging

    // stage A: thread -> row r = tid/2, k-half kh (64 cols)
    {
        int r = tid >> 1;
        int kh = (tid & 1) << 6;
        int gr = row0 + r;
        const float* Arow = A + (size_t)gr * 128;
        uint32_t* ah = Ahi + r * WSTRIDE + (kh >> 1);
        uint32_t* al = Alo + r * WSTRIDE + (kh >> 1);
#pragma unroll
        for (int g = 0; g < 16; g++) {
            int k = kh + g * 4;
            float4 v = make_float4(0.f, 0.f, 0.f, 0.f);
            if (gr < NN) {
                v = *(const float4*)(Arow + k);
                if (TR) {
                    v.x = fmaxf(fmaf(v.x, s_sc[k + 0], s_sh[k + 0]), 0.f);
                    v.y = fmaxf(fmaf(v.y, s_sc[k + 1], s_sh[k + 1]), 0.f);
                    v.z = fmaxf(fmaf(v.z, s_sc[k + 2], s_sh[k + 2]), 0.f);
                    v.w = fmaxf(fmaf(v.w, s_sc[k + 3], s_sh[k + 3]), 0.f);
                }
            }
            uint32_t l0, l1;
            uint32_t h0 = pack2(v.x, v.y, l0);
            uint32_t h1 = pack2(v.z, v.w, l1);
            ah[g * 2] = h0; ah[g * 2 + 1] = h1;
            al[g * 2] = l0; al[g * 2 + 1] = l1;
        }
    }
    __syncthreads();

    // MMA: warp wid -> rows wid*16..+15; 16 n-tiles of 8; 8 k-chunks of 16
    const int wid = tid >> 5, lane = tid & 31;
    const int qr = lane >> 2, ql = lane & 3;
    const int mrow = wid * 16;
    float acc[16][4];
#pragma unroll
    for (int i = 0; i < 16; i++)
#pragma unroll
        for (int j = 0; j < 4; j++) acc[i][j] = 0.f;

    const uint32_t* Ah0 = Ahi + (mrow + qr) * WSTRIDE;
    const uint32_t* Ah1 = Ahi + (mrow + qr + 8) * WSTRIDE;
    const uint32_t* Al0 = Alo + (mrow + qr) * WSTRIDE;
    const uint32_t* Al1 = Alo + (mrow + qr + 8) * WSTRIDE;

#pragma unroll
    for (int kc = 0; kc < 8; kc++) {
        int kb = kc * 8;
        uint32_t ah0 = Ah0[kb + ql],     ah1 = Ah1[kb + ql];
        uint32_t ah2 = Ah0[kb + 4 + ql], ah3 = Ah1[kb + 4 + ql];
        uint32_t al0 = Al0[kb + ql],     al1 = Al1[kb + ql];
        uint32_t al2 = Al0[kb + 4 + ql], al3 = Al1[kb + 4 + ql];
#pragma unroll
        for (int nt = 0; nt < 16; nt++) {
            const uint32_t* Bh = Bhi + (nt * 8 + qr) * WSTRIDE;
            const uint32_t* Bl = Blo + (nt * 8 + qr) * WSTRIDE;
            uint32_t bh0 = Bh[kb + ql], bh1 = Bh[kb + 4 + ql];
            uint32_t bl0 = Bl[kb + ql], bl1 = Bl[kb + 4 + ql];
            MMA_BF16(acc[nt], ah0, ah1, ah2, ah3, bh0, bh1);
            MMA_BF16(acc[nt], ah0, ah1, ah2, ah3, bl0, bl1);
            MMA_BF16(acc[nt], al0, al1, al2, al3, bh0, bh1);
        }
    }

    // epilogue: write fp16x2 pairs (pair p = features 2p, 2p+1)
    int r0 = row0 + mrow + qr;
    int r1 = r0 + 8;
#pragma unroll
    for (int nt = 0; nt < 16; nt++) {
        int p = nt * 4 + ql;   // pair index; features c=2p, 2p+1
        if (r0 < NN) g_bufA16[(size_t)r0 * 64 + p] = packhf(acc[nt][0], acc[nt][1]);
        if (r1 < NN) g_bufA16[(size_t)r1 * 64 + p] = packhf(acc[nt][2], acc[nt][3]);
    }
}

__global__ __launch_bounds__(256) void k_gemm_x(const float* __restrict__ A) {
    gemm_mma<false>(A, nullptr, nullptr);
}

template <int L>
__global__ __launch_bounds__(256) void k_gemm_h() {
    gemm_mma<true>(g_bufB, g_scale[L], g_shift[L]);
}

// ---------------- aggregation (fp16 gather) with fused BN partial stats ----------
__global__ __launch_bounds__(256) void k_agg() {
    __shared__ float s_red[8][128];
    int gt = blockIdx.x * blockDim.x + threadIdx.x;
    int w = gt >> 5, lane = threadIdx.x & 31, wid = threadIdx.x >> 5;
    int s0 = g_rowstart[w], s1 = g_rowstart[w + 1];
    float4 acc = make_float4(0.f, 0.f, 0.f, 0.f);
    for (int j = s0; j < s1; j++) {
        int2 e = g_csr[j];
        float nm = __int_as_float(e.y);
        uint2 hv = *(const uint2*)(g_bufA16 + (size_t)e.x * 64 + lane * 2);
        float2 f0 = __half22float2(*reinterpret_cast<__half2*>(&hv.x));
        float2 f1 = __half22float2(*reinterpret_cast<__half2*>(&hv.y));
        acc.x = fmaf(nm, f0.x, acc.x);
        acc.y = fmaf(nm, f0.y, acc.y);
        acc.z = fmaf(nm, f1.x, acc.z);
        acc.w = fmaf(nm, f1.y, acc.w);
    }
    int fo = lane * 4;
    *(float4*)(g_bufB + (size_t)w * 128 + fo) = acc;
    *(float4*)&s_red[wid][fo] = acc;
    __syncthreads();
    int t = threadIdx.x;
    if (t < 128) {
        float s = 0.f, q = 0.f;
#pragma unroll
        for (int r = 0; r < 8; r++) {
            float v = s_red[r][t];
            s += v;
            q = fmaf(v, v, q);
        }
        int slot = (blockIdx.x & 255) * 128 + t;
        atomicAdd(&g_psum[slot], s);
        atomicAdd(&g_psq[slot], q);
    }
}

// ---------------- layer end: BN finalize (+psum re-zero) + prep next W / zero pool ----
template <int L, bool PREPW, bool ZPOOL>
__global__ void k_layer_end(const float* __restrict__ gamma,
                            const float* __restrict__ beta,
                            const float* __restrict__ Wn) {
    int tid = threadIdx.x, bid = blockIdx.x;
    if (bid == 0) {
        if (tid < 128) {
            int f = tid;
            float s = 0.f, q = 0.f;
            for (int b = 0; b < 256; b++) {
                int o = b * 128 + f;
                s += g_psum[o];
                q += g_psq[o];
                g_psum[o] = 0.f;
                g_psq[o] = 0.f;
            }
            float m = s / (float)NN;
            float var = fmaxf(q / (float)NN - m * m, 0.f);
            float sc = gamma[f] * rsqrtf(var + BNEPS);
            g_scale[L][f] = sc;
            g_shift[L][f] = beta[f] - m * sc;   // GCN bias cancels inside BN
        }
    } else {
        int idx = (bid - 1) * 256 + tid;
        if (PREPW) {
            if (idx < 128 * 64) prepW_one(Wn, idx);
        }
        if (ZPOOL) {
            if (idx < GG * HH) g_pooled[idx] = 0.f;
            if (idx < GG) g_counts[idx] = 0;
        }
    }
}

// ---------------- pooling (BN+ReLU fused, segment-accumulated: batch is sorted) ----
__global__ __launch_bounds__(256) void k_pool() {
    int gw = (blockIdx.x * blockDim.x + threadIdx.x) >> 5;
    int lane = threadIdx.x & 31;
    int n0 = gw * 16;
    if (n0 >= NN) return;
    int n1 = n0 + 16;
    if (n1 > NN) n1 = NN;
    int fo = lane * 4;
    float4 sc = *(const float4*)&g_scale[2][fo];
    float4 sh = *(const float4*)&g_shift[2][fo];
    int cur = g_batch32[n0];
    float4 acc = make_float4(0.f, 0.f, 0.f, 0.f);
    int cnt = 0;
    for (int n = n0; n < n1; n++) {
        int gb = g_batch32[n];
        if (gb != cur) {
            float* base = g_pooled + (size_t)cur * 128 + fo;
            atomicAdd(base + 0, acc.x);
            atomicAdd(base + 1, acc.y);
            atomicAdd(base + 2, acc.z);
            atomicAdd(base + 3, acc.w);
            if (lane == 0) atomicAdd(&g_counts[cur], cnt);
            acc = make_float4(0.f, 0.f, 0.f, 0.f);
            cnt = 0;
            cur = gb;
        }
        float4 v = *(const float4*)(g_bufB + (size_t)n * 128 + fo);
        acc.x += fmaxf(fmaf(v.x, sc.x, sh.x), 0.f);
        acc.y += fmaxf(fmaf(v.y, sc.y, sh.y), 0.f);
        acc.z += fmaxf(fmaf(v.z, sc.z, sh.z), 0.f);
        acc.w += fmaxf(fmaf(v.w, sc.w, sh.w), 0.f);
        cnt++;
    }
    float* base = g_pooled + (size_t)cur * 128 + fo;
    atomicAdd(base + 0, acc.x);
    atomicAdd(base + 1, acc.y);
    atomicAdd(base + 2, acc.z);
    atomicAdd(base + 3, acc.w);
    if (lane == 0) atomicAdd(&g_counts[cur], cnt);
}

// ---------------- head ----------------
__global__ void k_headstats(const float* __restrict__ gp,
                            const float* __restrict__ bep) {
    int f = threadIdx.x;
    float s = 0.f, q = 0.f;
    for (int r = 0; r < GG; r++) {
        int c = g_counts[r];
        float invc = 1.f / (float)(c > 0 ? c : 1);
        float v = g_pooled[(size_t)r * 128 + f] * invc;
        s += v;
        q = fmaf(v, v, q);
    }
    float m = s / (float)GG;
    float var = fmaxf(q / (float)GG - m * m, 0.f);
    float sc = gp[f] * rsqrtf(var + BNEPS);
    g_scaleP[f] = sc;
    g_shiftP[f] = bep[f] - m * sc;
}

__global__ void k_head(const float* __restrict__ lw1, const float* __restrict__ lb1,
                       const float* __restrict__ lw2, const float* __restrict__ lb2,
                       float* __restrict__ out) {
    __shared__ float zn[128], y1[128], lg[CC], lse;
    int r = blockIdx.x, t = threadIdx.x;
    int c = g_counts[r];
    float invc = 1.f / (float)(c > 0 ? c : 1);
    zn[t] = fmaf(g_pooled[(size_t)r * 128 + t] * invc, g_scaleP[t], g_shiftP[t]);
    __syncthreads();
    float a = lb1[t];
#pragma unroll 16
    for (int k = 0; k < 128; k++) a = fmaf(zn[k], lw1[(size_t)k * 128 + t], a);
    y1[t] = fmaxf(a, 0.f);
    __syncthreads();
    if (t < CC) {
        float a2 = lb2[t];
#pragma unroll 16
        for (int k = 0; k < 128; k++) a2 = fmaf(y1[k], lw2[(size_t)k * CC + t], a2);
        lg[t] = a2;
    }
    __syncthreads();
    if (t == 0) {
        float m = lg[0];
        for (int i = 1; i < CC; i++) m = fmaxf(m, lg[i]);
        float s = 0.f;
        for (int i = 0; i < CC; i++) s += expf(lg[i] - m);
        lse = m + logf(s);
    }
    __syncthreads();
    if (t < CC) out[(size_t)r * CC + t] = lg[t] - lse;
}

// ---------------- launch ----------------
extern "C" void kernel_launch(void* const* d_in, const int* in_sizes, int n_in,
                              void* d_out, int out_size) {
    const float* x   = (const float*)d_in[0];
    const void*  ei  = d_in[1];
    const void*  bt  = d_in[2];
    const float* W1  = (const float*)d_in[3];
    const float* g1  = (const float*)d_in[5];
    const float* be1 = (const float*)d_in[6];
    const float* W2  = (const float*)d_in[7];
    const float* g2  = (const float*)d_in[9];
    const float* be2 = (const float*)d_in[10];
    const float* W3  = (const float*)d_in[11];
    const float* g3  = (const float*)d_in[13];
    const float* be3 = (const float*)d_in[14];
    const float* gp  = (const float*)d_in[15];
    const float* bep = (const float*)d_in[16];
    const float* lw1 = (const float*)d_in[17];
    const float* lb1 = (const float*)d_in[18];
    const float* lw2 = (const float*)d_in[19];
    const float* lb2 = (const float*)d_in[20];
    float* out = (float*)d_out;

    cudaFuncSetAttribute((const void*)k_gemm_x,
                         cudaFuncAttributeMaxDynamicSharedMemorySize, SMEM_DYN);
    cudaFuncSetAttribute((const void*)k_gemm_h<0>,
                         cudaFuncAttributeMaxDynamicSharedMemorySize, SMEM_DYN);
    cudaFuncSetAttribute((const void*)k_gemm_h<1>,
                         cudaFuncAttributeMaxDynamicSharedMemorySize, SMEM_DYN);

    const int EB  = (EE + 255) / 256;          // 6250
    const int WB  = (NN * 32 + 255) / 256;     // 12500
    const int GMB = (NN + 127) / 128;          // 782
    const int PB  = ((NN + 15) / 16 + 7) / 8;  // pool: 16 nodes/warp

    k_prep0<<<519, 256>>>(ei, bt, W1);        // detect + prepW(W1) + zero psum + node init
    k_count<<<EB, 256>>>(ei);                 // degree count from edge_index
    k_scan1<<<98, 1024>>>();                  // + dis
    k_gemm_x<<<GMB, 256, SMEM_DYN>>>(x);      // <- profiled launch (slot 4)
    k_scan2<<<1, 128>>>();
    k_scan3<<<98, 1024>>>();                  // + self-loop insert
    k_build<<<EB, 256>>>(ei);

    // layer 1
    k_agg<<<WB, 256>>>();
    k_layer_end<0, true, false><<<33, 256>>>(g1, be1, W2);
    // layer 2 (BN+ReLU of layer 1 fused into GEMM A staging)
    k_gemm_h<0><<<GMB, 256, SMEM_DYN>>>();
    k_agg<<<WB, 256>>>();
    k_layer_end<1, true, false><<<33, 256>>>(g2, be2, W3);
    // layer 3
    k_gemm_h<1><<<GMB, 256, SMEM_DYN>>>();
    k_agg<<<WB, 256>>>();
    k_layer_end<2, false, true><<<257, 256>>>(g3, be3, nullptr);

    // pool + head
    k_pool<<<PB, 256>>>();
    k_headstats<<<1, 128>>>(gp, bep);
    k_head<<<GG, 128>>>(lw1, lb1, lw2, lb2, out);
}

// round 17
// speedup vs baseline: 1.1326x; 1.0173x over previous
#include <cuda_runtime.h>
#include <cuda_bf16.h>
#include <cuda_fp16.h>
#include <stdint.h>

#define NN 100000
#define EE 1600000
#define HH 128
#define GG 512
#define CC 10
#define TOT (EE + NN)
#define BNEPS 1e-5f

// W^T padded fp16x2 layout: u32[n][68] (64 k-pairs + 4 pad); row = 272 bytes
#define WSTRIDE 68
#define WELEMS (128 * WSTRIDE)   // 8704 u32

// ---------------- scratch (static device globals; no allocation) ----------------
__device__ int   g_is64;
__device__ int   g_batch32[NN];
__device__ int   g_deg[NN];
__device__ float g_dis[NN];
__device__ int   g_rowstart[NN + 1];
__device__ int   g_fill[NN];
__device__ int   g_blocksum[128];
__device__ int   g_blockoff[128];
__device__ int2  g_csr[TOT];                    // (src, norm-bits)
__device__ uint32_t g_bufA16[(size_t)NN * 64];  // GEMM output, fp16x2 (feature pairs)
__device__ float g_bufB[(size_t)NN * HH];       // aggregation output (pre-BN, fp32)
__device__ float g_psum[256 * HH];
__device__ float g_psq[256 * HH];
__device__ float g_scale[3][HH];
__device__ float g_shift[3][HH];
__device__ float g_pooled[GG * HH];
__device__ int   g_counts[GG];
__device__ float g_scaleP[HH];
__device__ float g_shiftP[HH];
__device__ __align__(16) uint32_t g_Whi32[WELEMS];   // fp16 hi of W^T
__device__ __align__(16) uint32_t g_Wlo32[WELEMS];   // fp16 lo (residual) of W^T

// ---------------- fp16 helpers ----------------
__device__ __forceinline__ uint32_t packhf(float a, float b) {
    __half2 h2 = __floats2half2_rn(a, b);
    return *reinterpret_cast<uint32_t*>(&h2);
}

// split W^T into fp16 hi + fp16 residual lo (22 effective mantissa bits)
__device__ __forceinline__ void prepW_one(const float* __restrict__ W, int idx) {
    int n = idx >> 6, kp = idx & 63;
    float v0 = W[(size_t)(kp * 2) * 128 + n];
    float v1 = W[(size_t)(kp * 2 + 1) * 128 + n];
    __half h0 = __float2half_rn(v0), h1 = __float2half_rn(v1);
    __half l0 = __float2half_rn(v0 - __half2float(h0));
    __half l1 = __float2half_rn(v1 - __half2float(h1));
    uint32_t hi = (uint32_t)__half_as_ushort(h0) | ((uint32_t)__half_as_ushort(h1) << 16);
    uint32_t lo = (uint32_t)__half_as_ushort(l0) | ((uint32_t)__half_as_ushort(l1) << 16);
    g_Whi32[n * WSTRIDE + kp] = hi;
    g_Wlo32[n * WSTRIDE + kp] = lo;
}

// ---------------- fused prologue: detect + prepW(W1) + zero psum + node init ----
__global__ void k_prep0(const void* ei, const void* bt, const float* __restrict__ W) {
    __shared__ int s_is64;
    int tid = threadIdx.x, bid = blockIdx.x;
    if (tid == 0) {
        const long long* p = (const long long*)ei;
        int ok = 1;
        for (int i = 0; i < 64; i++) {
            long long v = p[i];
            if (v < 0 || v >= NN) { ok = 0; break; }
        }
        s_is64 = ok;
        if (bid == 0) g_is64 = ok;
    }
    __syncthreads();
    int idx = bid * 256 + tid;
    if (idx < 128 * 64) prepW_one(W, idx);
    if (idx < 256 * HH) { g_psum[idx] = 0.f; g_psq[idx] = 0.f; }
    if (bid >= 128) {
        int i = (bid - 128) * 256 + tid;
        if (i < NN) {
            g_deg[i] = 1;   // self-loop
            if (s_is64) g_batch32[i] = (int)((const long long*)bt)[i];
            else        g_batch32[i] = ((const int*)bt)[i];
        }
    }
}

__global__ void k_count(const void* ei) {   // degree count straight from edge_index
    int e = blockIdx.x * blockDim.x + threadIdx.x;
    if (e >= EE) return;
    int d;
    if (g_is64) d = (int)((const long long*)ei)[EE + e];
    else        d = ((const int*)ei)[EE + e];
    atomicAdd(&g_deg[d], 1);
}

__global__ void k_scan1() {   // inclusive scan of deg per 1024-chunk; also dis
    __shared__ int s[1024];
    int i = blockIdx.x * 1024 + threadIdx.x;
    int v = (i < NN) ? g_deg[i] : 0;
    if (i < NN) g_dis[i] = rsqrtf((float)v);
    s[threadIdx.x] = v;
    __syncthreads();
    for (int off = 1; off < 1024; off <<= 1) {
        int t = (threadIdx.x >= off) ? s[threadIdx.x - off] : 0;
        __syncthreads();
        s[threadIdx.x] += t;
        __syncthreads();
    }
    if (i < NN) g_rowstart[i] = s[threadIdx.x];
    if (threadIdx.x == 1023) g_blocksum[blockIdx.x] = s[1023];
}

__global__ void k_scan2() {
    __shared__ int s[128];
    int t = threadIdx.x;
    int v = (t < 98) ? g_blocksum[t] : 0;
    s[t] = v;
    __syncthreads();
    for (int off = 1; off < 128; off <<= 1) {
        int tv = (t >= off) ? s[t - off] : 0;
        __syncthreads();
        s[t] += tv;
        __syncthreads();
    }
    g_blockoff[t] = s[t] - v;
}

__global__ void k_scan3() {   // finalize rowstart + insert self-loop + fill=1
    int i = blockIdx.x * 1024 + threadIdx.x;
    if (i < NN) {
        int rs = g_rowstart[i] - g_deg[i] + g_blockoff[blockIdx.x];
        g_rowstart[i] = rs;
        float d = g_dis[i];
        g_csr[rs] = make_int2(i, __float_as_int(d * d));
        g_fill[i] = 1;
        if (i == NN - 1) g_rowstart[NN] = TOT;
    }
}

__global__ void k_build(const void* ei) {
    int e = blockIdx.x * blockDim.x + threadIdx.x;
    if (e >= EE) return;
    int s, d;
    if (g_is64) {
        const long long* p = (const long long*)ei;
        s = (int)p[e];
        d = (int)p[EE + e];
    } else {
        const int* p = (const int*)ei;
        s = p[e];
        d = p[EE + e];
    }
    int p = atomicAdd(&g_fill[d], 1);
    g_csr[g_rowstart[d] + p] = make_int2(s, __float_as_int(g_dis[s] * g_dis[d]));
}

// ---------------- GEMM: A fp16 x W (fp16 hi+lo), 2-term HMMA, 2 CTAs/SM ----------
#define MMA_F16(d, a0, a1, a2, a3, b0, b1)                               \
    asm volatile(                                                        \
        "mma.sync.aligned.m16n8k16.row.col.f32.f16.f16.f32 "             \
        "{%0,%1,%2,%3},{%4,%5,%6,%7},{%8,%9},{%0,%1,%2,%3};"             \
        : "+f"(d[0]), "+f"(d[1]), "+f"(d[2]), "+f"(d[3])                 \
        : "r"(a0), "r"(a1), "r"(a2), "r"(a3), "r"(b0), "r"(b1))

#define SMEM_DYN (3 * WELEMS * 4)   // Ahi, Bhi, Blo = 104448 B -> 2 CTAs/SM

// bufA16[N,64 pairs] = T(A)[N,128] @ W[128,128]; T = identity or BN(scale,shift)+ReLU.
template <bool TR>
__device__ __forceinline__ void gemm_mma(const float* __restrict__ A,
                                         const float* __restrict__ scl,
                                         const float* __restrict__ shf) {
    extern __shared__ uint32_t sm[];
    uint32_t* Ahi = sm;
    uint32_t* Bhi = sm + WELEMS;
    uint32_t* Blo = sm + 2 * WELEMS;
    __shared__ float s_sc[128], s_sh[128];

    const int tid = threadIdx.x;
    const int row0 = blockIdx.x * 128;

    if (TR && tid < 128) { s_sc[tid] = scl[tid]; s_sh[tid] = shf[tid]; }

    // copy pre-split W into smem (uint4; 2176 uint4 per buffer)
    {
        const uint4* src_h = (const uint4*)g_Whi32;
        const uint4* src_l = (const uint4*)g_Wlo32;
        uint4* dst_h = (uint4*)Bhi;
        uint4* dst_l = (uint4*)Blo;
#pragma unroll
        for (int i = 0; i < 9; i++) {
            int q = tid + i * 256;
            if (q < WELEMS / 4) { dst_h[q] = src_h[q]; dst_l[q] = src_l[q]; }
        }
    }
    if (TR) __syncthreads();   // s_sc/s_sh visible for A staging

    // stage A (fp16): thread -> row r = tid/2, k-half kh (64 cols)
    {
        int r = tid >> 1;
        int kh = (tid & 1) << 6;
        int gr = row0 + r;
        const float* Arow = A + (size_t)gr * 128;
        uint32_t* ah = Ahi + r * WSTRIDE + (kh >> 1);
#pragma unroll
        for (int g = 0; g < 16; g++) {
            int k = kh + g * 4;
            float4 v = make_float4(0.f, 0.f, 0.f, 0.f);
            if (gr < NN) {
                v = *(const float4*)(Arow + k);
                if (TR) {
                    v.x = fmaxf(fmaf(v.x, s_sc[k + 0], s_sh[k + 0]), 0.f);
                    v.y = fmaxf(fmaf(v.y, s_sc[k + 1], s_sh[k + 1]), 0.f);
                    v.z = fmaxf(fmaf(v.z, s_sc[k + 2], s_sh[k + 2]), 0.f);
                    v.w = fmaxf(fmaf(v.w, s_sc[k + 3], s_sh[k + 3]), 0.f);
                }
            }
            ah[g * 2]     = packhf(v.x, v.y);
            ah[g * 2 + 1] = packhf(v.z, v.w);
        }
    }
    __syncthreads();

    // MMA: warp wid -> rows wid*16..+15; 16 n-tiles of 8; 8 k-chunks of 16
    const int wid = tid >> 5, lane = tid & 31;
    const int qr = lane >> 2, ql = lane & 3;
    const int mrow = wid * 16;
    float acc[16][4];
#pragma unroll
    for (int i = 0; i < 16; i++)
#pragma unroll
        for (int j = 0; j < 4; j++) acc[i][j] = 0.f;

    const uint32_t* Ah0 = Ahi + (mrow + qr) * WSTRIDE;
    const uint32_t* Ah1 = Ahi + (mrow + qr + 8) * WSTRIDE;

#pragma unroll
    for (int kc = 0; kc < 8; kc++) {
        int kb = kc * 8;
        uint32_t a0 = Ah0[kb + ql],     a1 = Ah1[kb + ql];
        uint32_t a2 = Ah0[kb + 4 + ql], a3 = Ah1[kb + 4 + ql];
#pragma unroll
        for (int nt = 0; nt < 16; nt++) {
            const uint32_t* Bh = Bhi + (nt * 8 + qr) * WSTRIDE;
            const uint32_t* Bl = Blo + (nt * 8 + qr) * WSTRIDE;
            uint32_t bh0 = Bh[kb + ql], bh1 = Bh[kb + 4 + ql];
            uint32_t bl0 = Bl[kb + ql], bl1 = Bl[kb + 4 + ql];
            MMA_F16(acc[nt], a0, a1, a2, a3, bh0, bh1);
            MMA_F16(acc[nt], a0, a1, a2, a3, bl0, bl1);
        }
    }

    // epilogue: write fp16x2 pairs (pair p = features 2p, 2p+1)
    int r0 = row0 + mrow + qr;
    int r1 = r0 + 8;
#pragma unroll
    for (int nt = 0; nt < 16; nt++) {
        int p = nt * 4 + ql;   // pair index; features c=2p, 2p+1
        if (r0 < NN) g_bufA16[(size_t)r0 * 64 + p] = packhf(acc[nt][0], acc[nt][1]);
        if (r1 < NN) g_bufA16[(size_t)r1 * 64 + p] = packhf(acc[nt][2], acc[nt][3]);
    }
}

__global__ __launch_bounds__(256) void k_gemm_x(const float* __restrict__ A) {
    gemm_mma<false>(A, nullptr, nullptr);
}

template <int L>
__global__ __launch_bounds__(256) void k_gemm_h() {
    gemm_mma<true>(g_bufB, g_scale[L], g_shift[L]);
}

// ---------------- aggregation (fp16 gather) with fused BN partial stats ----------
__global__ __launch_bounds__(256) void k_agg() {
    __shared__ float s_red[8][128];
    int gt = blockIdx.x * blockDim.x + threadIdx.x;
    int w = gt >> 5, lane = threadIdx.x & 31, wid = threadIdx.x >> 5;
    int s0 = g_rowstart[w], s1 = g_rowstart[w + 1];
    float4 acc = make_float4(0.f, 0.f, 0.f, 0.f);
    for (int j = s0; j < s1; j++) {
        int2 e = g_csr[j];
        float nm = __int_as_float(e.y);
        uint2 hv = *(const uint2*)(g_bufA16 + (size_t)e.x * 64 + lane * 2);
        float2 f0 = __half22float2(*reinterpret_cast<__half2*>(&hv.x));
        float2 f1 = __half22float2(*reinterpret_cast<__half2*>(&hv.y));
        acc.x = fmaf(nm, f0.x, acc.x);
        acc.y = fmaf(nm, f0.y, acc.y);
        acc.z = fmaf(nm, f1.x, acc.z);
        acc.w = fmaf(nm, f1.y, acc.w);
    }
    int fo = lane * 4;
    *(float4*)(g_bufB + (size_t)w * 128 + fo) = acc;
    *(float4*)&s_red[wid][fo] = acc;
    __syncthreads();
    int t = threadIdx.x;
    if (t < 128) {
        float s = 0.f, q = 0.f;
#pragma unroll
        for (int r = 0; r < 8; r++) {
            float v = s_red[r][t];
            s += v;
            q = fmaf(v, v, q);
        }
        int slot = (blockIdx.x & 255) * 128 + t;
        atomicAdd(&g_psum[slot], s);
        atomicAdd(&g_psq[slot], q);
    }
}

// ---------------- layer end: BN finalize (+psum re-zero) + prep next W / zero pool ----
template <int L, bool PREPW, bool ZPOOL>
__global__ void k_layer_end(const float* __restrict__ gamma,
                            const float* __restrict__ beta,
                            const float* __restrict__ Wn) {
    int tid = threadIdx.x, bid = blockIdx.x;
    if (bid == 0) {
        if (tid < 128) {
            int f = tid;
            float s = 0.f, q = 0.f;
            for (int b = 0; b < 256; b++) {
                int o = b * 128 + f;
                s += g_psum[o];
                q += g_psq[o];
                g_psum[o] = 0.f;
                g_psq[o] = 0.f;
            }
            float m = s / (float)NN;
            float var = fmaxf(q / (float)NN - m * m, 0.f);
            float sc = gamma[f] * rsqrtf(var + BNEPS);
            g_scale[L][f] = sc;
            g_shift[L][f] = beta[f] - m * sc;   // GCN bias cancels inside BN
        }
    } else {
        int idx = (bid - 1) * 256 + tid;
        if (PREPW) {
            if (idx < 128 * 64) prepW_one(Wn, idx);
        }
        if (ZPOOL) {
            if (idx < GG * HH) g_pooled[idx] = 0.f;
            if (idx < GG) g_counts[idx] = 0;
        }
    }
}

// ---------------- pooling (BN+ReLU fused, segment-accumulated: batch is sorted) ----
__global__ __launch_bounds__(256) void k_pool() {
    int gw = (blockIdx.x * blockDim.x + threadIdx.x) >> 5;
    int lane = threadIdx.x & 31;
    int n0 = gw * 16;
    if (n0 >= NN) return;
    int n1 = n0 + 16;
    if (n1 > NN) n1 = NN;
    int fo = lane * 4;
    float4 sc = *(const float4*)&g_scale[2][fo];
    float4 sh = *(const float4*)&g_shift[2][fo];
    int cur = g_batch32[n0];
    float4 acc = make_float4(0.f, 0.f, 0.f, 0.f);
    int cnt = 0;
    for (int n = n0; n < n1; n++) {
        int gb = g_batch32[n];
        if (gb != cur) {
            float* base = g_pooled + (size_t)cur * 128 + fo;
            atomicAdd(base + 0, acc.x);
            atomicAdd(base + 1, acc.y);
            atomicAdd(base + 2, acc.z);
            atomicAdd(base + 3, acc.w);
            if (lane == 0) atomicAdd(&g_counts[cur], cnt);
            acc = make_float4(0.f, 0.f, 0.f, 0.f);
            cnt = 0;
            cur = gb;
        }
        float4 v = *(const float4*)(g_bufB + (size_t)n * 128 + fo);
        acc.x += fmaxf(fmaf(v.x, sc.x, sh.x), 0.f);
        acc.y += fmaxf(fmaf(v.y, sc.y, sh.y), 0.f);
        acc.z += fmaxf(fmaf(v.z, sc.z, sh.z), 0.f);
        acc.w += fmaxf(fmaf(v.w, sc.w, sh.w), 0.f);
        cnt++;
    }
    float* base = g_pooled + (size_t)cur * 128 + fo;
    atomicAdd(base + 0, acc.x);
    atomicAdd(base + 1, acc.y);
    atomicAdd(base + 2, acc.z);
    atomicAdd(base + 3, acc.w);
    if (lane == 0) atomicAdd(&g_counts[cur], cnt);
}

// ---------------- head ----------------
__global__ void k_headstats(const float* __restrict__ gp,
                            const float* __restrict__ bep) {
    int f = threadIdx.x;
    float s = 0.f, q = 0.f;
    for (int r = 0; r < GG; r++) {
        int c = g_counts[r];
        float invc = 1.f / (float)(c > 0 ? c : 1);
        float v = g_pooled[(size_t)r * 128 + f] * invc;
        s += v;
        q = fmaf(v, v, q);
    }
    float m = s / (float)GG;
    float var = fmaxf(q / (float)GG - m * m, 0.f);
    float sc = gp[f] * rsqrtf(var + BNEPS);
    g_scaleP[f] = sc;
    g_shiftP[f] = bep[f] - m * sc;
}

__global__ void k_head(const float* __restrict__ lw1, const float* __restrict__ lb1,
                       const float* __restrict__ lw2, const float* __restrict__ lb2,
                       float* __restrict__ out) {
    __shared__ float zn[128], y1[128], lg[CC], lse;
    int r = blockIdx.x, t = threadIdx.x;
    int c = g_counts[r];
    float invc = 1.f / (float)(c > 0 ? c : 1);
    zn[t] = fmaf(g_pooled[(size_t)r * 128 + t] * invc, g_scaleP[t], g_shiftP[t]);
    __syncthreads();
    float a = lb1[t];
#pragma unroll 16
    for (int k = 0; k < 128; k++) a = fmaf(zn[k], lw1[(size_t)k * 128 + t], a);
    y1[t] = fmaxf(a, 0.f);
    __syncthreads();
    if (t < CC) {
        float a2 = lb2[t];
#pragma unroll 16
        for (int k = 0; k < 128; k++) a2 = fmaf(y1[k], lw2[(size_t)k * CC + t], a2);
        lg[t] = a2;
    }
    __syncthreads();
    if (t == 0) {
        float m = lg[0];
        for (int i = 1; i < CC; i++) m = fmaxf(m, lg[i]);
        float s = 0.f;
        for (int i = 0; i < CC; i++) s += expf(lg[i] - m);
        lse = m + logf(s);
    }
    __syncthreads();
    if (t < CC) out[(size_t)r * CC + t] = lg[t] - lse;
}

// ---------------- launch ----------------
extern "C" void kernel_launch(void* const* d_in, const int* in_sizes, int n_in,
                              void* d_out, int out_size) {
    const float* x   = (const float*)d_in[0];
    const void*  ei  = d_in[1];
    const void*  bt  = d_in[2];
    const float* W1  = (const float*)d_in[3];
    const float* g1  = (const float*)d_in[5];
    const float* be1 = (const float*)d_in[6];
    const float* W2  = (const float*)d_in[7];
    const float* g2  = (const float*)d_in[9];
    const float* be2 = (const float*)d_in[10];
    const float* W3  = (const float*)d_in[11];
    const float* g3  = (const float*)d_in[13];
    const float* be3 = (const float*)d_in[14];
    const float* gp  = (const float*)d_in[15];
    const float* bep = (const float*)d_in[16];
    const float* lw1 = (const float*)d_in[17];
    const float* lb1 = (const float*)d_in[18];
    const float* lw2 = (const float*)d_in[19];
    const float* lb2 = (const float*)d_in[20];
    float* out = (float*)d_out;

    cudaFuncSetAttribute((const void*)k_gemm_x,
                         cudaFuncAttributeMaxDynamicSharedMemorySize, SMEM_DYN);
    cudaFuncSetAttribute((const void*)k_gemm_h<0>,
                         cudaFuncAttributeMaxDynamicSharedMemorySize, SMEM_DYN);
    cudaFuncSetAttribute((const void*)k_gemm_h<1>,
                         cudaFuncAttributeMaxDynamicSharedMemorySize, SMEM_DYN);

    const int EB  = (EE + 255) / 256;          // 6250
    const int WB  = (NN * 32 + 255) / 256;     // 12500
    const int GMB = (NN + 127) / 128;          // 782
    const int PB  = ((NN + 15) / 16 + 7) / 8;  // pool: 16 nodes/warp

    k_prep0<<<519, 256>>>(ei, bt, W1);        // detect + prepW(W1) + zero psum + node init
    k_count<<<EB, 256>>>(ei);                 // degree count from edge_index
    k_scan1<<<98, 1024>>>();                  // + dis
    k_gemm_x<<<GMB, 256, SMEM_DYN>>>(x);      // <- profiled launch (slot 4)
    k_scan2<<<1, 128>>>();
    k_scan3<<<98, 1024>>>();                  // + self-loop insert
    k_build<<<EB, 256>>>(ei);

    // layer 1
    k_agg<<<WB, 256>>>();
    k_layer_end<0, true, false><<<33, 256>>>(g1, be1, W2);
    // layer 2 (BN+ReLU of layer 1 fused into GEMM A staging)
    k_gemm_h<0><<<GMB, 256, SMEM_DYN>>>();
    k_agg<<<WB, 256>>>();
    k_layer_end<1, true, false><<<33, 256>>>(g2, be2, W3);
    // layer 3
    k_gemm_h<1><<<GMB, 256, SMEM_DYN>>>();
    k_agg<<<WB, 256>>>();
    k_layer_end<2, false, true><<<257, 256>>>(g3, be3, nullptr);

    // pool + head
    k_pool<<<PB, 256>>>();
    k_headstats<<<1, 128>>>(gp, bep);
    k_head<<<GG, 128>>>(lw1, lb1, lw2, lb2, out);
}